// round 17
// baseline (speedup 1.0000x reference)
#include <cuda_runtime.h>
#include <cstdint>
#include <math_constants.h>

#define NSEG 128
#define P    512
#define D    64
#define KT   15
#define NC   8
#define NT   1024
#define NW   (NT/32)
#define HALF4      4096                 // float4s per half-segment
#define HALF_BYTES (HALF4 * 16)        // 65536

struct SmemLayout {
    float4             data[HALF4];    // TMA half (points 256..511), 64KB
    unsigned long long mbar;
    float              sdist[P];
    int                slab[P];
    short              sidx[NC][16];
    int                sCnt[NC];
    int                sTaken[NC];
    float              sS[NC];
    float              sM[NC];
    float              sred[NW];
};

__device__ float g_accum  = 0.0f;   // running sum; reset by last CTA
__device__ int   g_ticket = 0;      // reset by last CTA

__device__ __forceinline__ uint32_t smem_u32(const void* p) {
    return (uint32_t)__cvta_generic_to_shared(p);
}
__device__ __forceinline__ void mbar_wait(uint32_t mbar, uint32_t parity) {
    asm volatile(
        "{\n\t.reg .pred P1;\n\t"
        "WAIT_LOOP_%=:\n\t"
        "mbarrier.try_wait.parity.acquire.cta.shared::cta.b64 P1, [%0], %1, 0x989680;\n\t"
        "@P1 bra.uni WAIT_DONE_%=;\n\t"
        "bra.uni WAIT_LOOP_%=;\n\t"
        "WAIT_DONE_%=:\n\t}"
        :: "r"(mbar), "r"(parity) : "memory");
}

__global__ __launch_bounds__(NT, 1)
void lmnn_fused_kernel(const float* __restrict__ center,
                       const float* __restrict__ outputs,
                       const int*   __restrict__ labels,
                       float*       __restrict__ out)
{
    extern __shared__ char smem_raw[];
    SmemLayout* sm = (SmemLayout*)smem_raw;

    const int seg  = blockIdx.x;
    const int t    = threadIdx.x;
    const int w    = t >> 5;
    const int lane = t & 31;
    const int col  = t & 15;

    const char* gseg = (const char*)outputs + (size_t)seg * P * D * 4;

    // ---- t0: mbar init; barrier; then TMA of the SECOND half (64KB) ----
    if (t == 0) {
        asm volatile("mbarrier.init.shared.b64 [%0], %1;"
                     :: "r"(smem_u32(&sm->mbar)), "r"(1u));
        asm volatile("fence.proxy.async.shared::cta;" ::: "memory");
    }
    __syncthreads();
    if (t == 0) {
        const uint32_t mb = smem_u32(&sm->mbar);
        asm volatile("mbarrier.arrive.expect_tx.shared.b64 _, [%0], %1;"
                     :: "r"(mb), "r"((uint32_t)HALF_BYTES) : "memory");
        asm volatile(
            "cp.async.bulk.shared::cluster.global.mbarrier::complete_tx::bytes "
            "[%0], [%1], %2, [%3];"
            :: "r"(smem_u32(sm->data)), "l"(gseg + HALF_BYTES),
               "r"((uint32_t)HALF_BYTES), "r"(mb) : "memory");
    }

    // ---- LDG half: 4 float4/thread, front-batched (both paths in flight) ----
    const float4* __restrict__ out4 = (const float4*)gseg;
    float4 v[4];
    #pragma unroll
    for (int s = 0; s < 4; ++s)
        v[s] = __ldcs(&out4[t + NT * s]);
    const float4 c4 = __ldg(&((const float4*)(center + seg * D))[col]);

    // ---- class scan on labels (warps 0..7), hidden under load flight ----
    // top_k over -dd has all finite entries equal (dist broadcast along k),
    // so jax tie-breaking selects the FIRST KT same-class indices.
    if (w < NC) {
        int lab[16];
        #pragma unroll
        for (int u = 0; u < 16; ++u)
            lab[u] = __ldg(&labels[seg * P + u * 32 + lane]);
        if (w == 0) {
            #pragma unroll
            for (int u = 0; u < 16; ++u)
                sm->slab[u * 32 + lane] = lab[u];
        }
        int cnt = 0, taken = 0;
        #pragma unroll
        for (int u = 0; u < 16; ++u) {
            const bool m = (lab[u] == w);
            const unsigned mask = __ballot_sync(0xffffffffu, m);
            const int pc = __popc(mask);
            const int need = KT - taken;
            if (need > 0) {
                const int rank = __popc(mask & ((1u << lane) - 1u));
                if (m && rank < need)
                    sm->sidx[w][taken + rank] = (short)(u * 32 + lane);
                taken += (pc < need) ? pc : need;
            }
            cnt += pc;
        }
        if (lane == 0) { sm->sCnt[w] = cnt; sm->sTaken[w] = taken; }
    }

    // ---- distances for LDG half (points 0..255): 16 lanes = one point ----
    #pragma unroll
    for (int s = 0; s < 4; ++s) {
        const int g = t + NT * s;                 // float4 idx 0..4095
        const float dx = v[s].x - c4.x;
        const float dy = v[s].y - c4.y;
        const float dz = v[s].z - c4.z;
        const float dw = v[s].w - c4.w;
        float part = dx * dx + dy * dy + dz * dz + dw * dw;
        part += __shfl_down_sync(0xffffffffu, part, 8);
        part += __shfl_down_sync(0xffffffffu, part, 4);
        part += __shfl_down_sync(0xffffffffu, part, 2);
        part += __shfl_down_sync(0xffffffffu, part, 1);
        if (col == 0) sm->sdist[g >> 4] = part;
    }

    // ---- distances for TMA half (points 256..511) from smem ----
    mbar_wait(smem_u32(&sm->mbar), 0u);
    #pragma unroll
    for (int s = 0; s < 4; ++s) {
        const int d = t + NT * s;                 // smem float4 idx 0..4095
        const float4 x = sm->data[d];
        const float dx = x.x - c4.x;
        const float dy = x.y - c4.y;
        const float dz = x.z - c4.z;
        const float dw = x.w - c4.w;
        float part = dx * dx + dy * dy + dz * dz + dw * dw;
        part += __shfl_down_sync(0xffffffffu, part, 8);
        part += __shfl_down_sync(0xffffffffu, part, 4);
        part += __shfl_down_sync(0xffffffffu, part, 2);
        part += __shfl_down_sync(0xffffffffu, part, 1);
        if (col == 0) sm->sdist[256 + (d >> 4)] = part;
    }
    __syncthreads();

    // ---- gather first-KT distances per class (warps 0..7) ----
    if (w < NC) {
        const int cnt   = sm->sCnt[w];
        const int taken = sm->sTaken[w];
        float d = (lane < KT)
                    ? ((lane < taken) ? sm->sdist[sm->sidx[w][lane]] : CUDART_INF_F)
                    : 0.0f;
        float S  = (lane < KT) ? d : 0.0f;
        float Mx = (lane < KT) ? d : -CUDART_INF_F;
        #pragma unroll
        for (int off = 16; off > 0; off >>= 1) {
            S += __shfl_xor_sync(0xffffffffu, S, off);
            Mx = fmaxf(Mx, __shfl_xor_sync(0xffffffffu, Mx, off));
        }
        if (lane == 0) {
            sm->sS[w] = (cnt > 0) ? S : 0.0f;
            sm->sM[w] = (cnt > 0) ? Mx : -CUDART_INF_F;
        }
    }
    __syncthreads();

    // ---- margin_seg = 1 + max over present classes ----
    float ms = -CUDART_INF_F;
    #pragma unroll
    for (int c = 0; c < NC; ++c)
        ms = fmaxf(ms, sm->sM[c]);
    ms += 1.0f;

    // ---- push term per point (first 512 threads) ----
    float term = 0.0f;
    if (t < P) {
        const int   cj = sm->slab[t];
        const float dv = sm->sdist[t];
        if (dv < ms)
            term = (float)(P - sm->sCnt[cj]) * fmaxf(1.0f + sm->sM[cj] - dv, 0.0f);
    }
    #pragma unroll
    for (int off = 16; off > 0; off >>= 1)
        term += __shfl_xor_sync(0xffffffffu, term, off);
    if (lane == 0) sm->sred[w] = term;
    __syncthreads();

    // ---- tail: accumulate into device scalar; last CTA emits result ----
    if (t == 0) {
        float push = 0.0f;
        #pragma unroll
        for (int k = 0; k < NW; ++k) push += sm->sred[k];
        float pull = 0.0f;
        #pragma unroll
        for (int c = 0; c < NC; ++c)
            pull += (float)sm->sCnt[c] * sm->sS[c];

        atomicAdd(&g_accum, pull + push);      // fire-and-forget REDG
        __threadfence();
        const int prev = atomicAdd(&g_ticket, 1);
        if (prev == NSEG - 1) {
            const float total = atomicExch(&g_accum, 0.0f);
            out[0] = total * (1.0f / (float)(NSEG * P));
            g_ticket = 0;                      // reset for next graph replay
        }
    }
}

extern "C" void kernel_launch(void* const* d_in, const int* in_sizes, int n_in,
                              void* d_out, int out_size)
{
    const float* center  = (const float*)d_in[0];  // (128, 64)    f32
    const float* outputs = (const float*)d_in[1];  // (128,512,64) f32
    const int*   labels  = (const int*)d_in[2];    // (128, 512)   i32

    cudaFuncSetAttribute(lmnn_fused_kernel,
                         cudaFuncAttributeMaxDynamicSharedMemorySize,
                         (int)sizeof(SmemLayout));
    lmnn_fused_kernel<<<NSEG, NT, sizeof(SmemLayout)>>>(
        center, outputs, labels, (float*)d_out);
}